// round 9
// baseline (speedup 1.0000x reference)
#include <cuda_runtime.h>
#include <cuda_fp16.h>
#include <cstdint>

// ---------------- problem constants ----------------
#define NROWS 8192
#define DIN   12544
#define HID   1024

// ---------------- GEMM tile config: 128x128 tile, 4 warps (64x64 warp tile) ----------------
#define BM 128
#define BN 128
#define BK 64
#define ROWB 144                           // 128B data + 16B pad (conflict-free ldmatrix)
#define STAGE_BYTES ((BM + BN) * ROWB)     // 36864
#define SMEM_BYTES (3 * STAGE_BYTES)       // 110592 -> 2 CTAs/SM

// ---------------- device scratch ----------------
__device__ __align__(256) __half g_Xh [(size_t)NROWS * DIN];
__device__ __align__(256) __half g_W1T[(size_t)HID * DIN];
__device__ __align__(256) __half g_W2T[(size_t)HID * HID];
__device__ __align__(256) __half g_H1 [(size_t)NROWS * HID];
__device__ __align__(256) float  g_H2 [(size_t)NROWS * HID];

// ---------------- PTX helpers ----------------
__device__ __forceinline__ uint32_t smem_u32(const void* p) {
    uint32_t a;
    asm("{ .reg .u64 t; cvta.to.shared.u64 t, %1; cvt.u32.u64 %0, t; }" : "=r"(a) : "l"(p));
    return a;
}

#define CP_ASYNC16(dst, src) \
    asm volatile("cp.async.cg.shared.global [%0], [%1], 16;" :: "r"(dst), "l"(src) : "memory")
#define CP_ASYNC_COMMIT() asm volatile("cp.async.commit_group;" ::: "memory")
#define CP_ASYNC_WAIT1()  asm volatile("cp.async.wait_group 1;" ::: "memory")

__device__ __forceinline__ void ldm_x4(uint32_t& r0, uint32_t& r1, uint32_t& r2, uint32_t& r3,
                                       uint32_t addr) {
    asm volatile("ldmatrix.sync.aligned.m8n8.x4.shared.b16 {%0,%1,%2,%3}, [%4];"
                 : "=r"(r0), "=r"(r1), "=r"(r2), "=r"(r3) : "r"(addr));
}

__device__ __forceinline__ void mma16816(float* d, const uint32_t* a, const uint32_t* b) {
    asm volatile(
        "mma.sync.aligned.m16n8k16.row.col.f32.f16.f16.f32 "
        "{%0,%1,%2,%3}, {%4,%5,%6,%7}, {%8,%9}, {%0,%1,%2,%3};"
        : "+f"(d[0]), "+f"(d[1]), "+f"(d[2]), "+f"(d[3])
        : "r"(a[0]), "r"(a[1]), "r"(a[2]), "r"(a[3]), "r"(b[0]), "r"(b[1]));
}

// ---------------- conversion kernels ----------------
__global__ void __launch_bounds__(256) f32_to_f16_kernel(const float* __restrict__ in,
                                                         __half* __restrict__ out, size_t n8) {
    size_t i = (size_t)blockIdx.x * blockDim.x + threadIdx.x;
    if (i >= n8) return;
    const float4* p = reinterpret_cast<const float4*>(in) + i * 2;
    float4 a = p[0], b = p[1];
    __half2 h0 = __floats2half2_rn(a.x, a.y), h1 = __floats2half2_rn(a.z, a.w);
    __half2 h2 = __floats2half2_rn(b.x, b.y), h3 = __floats2half2_rn(b.z, b.w);
    uint4 v;
    v.x = *reinterpret_cast<uint32_t*>(&h0);
    v.y = *reinterpret_cast<uint32_t*>(&h1);
    v.z = *reinterpret_cast<uint32_t*>(&h2);
    v.w = *reinterpret_cast<uint32_t*>(&h3);
    reinterpret_cast<uint4*>(out)[i] = v;
}

// in: [R, C] f32 row-major  ->  out: [C, R] f16 row-major (transpose + convert)
__global__ void __launch_bounds__(256) transpose_f32_to_f16(const float* __restrict__ in,
                                                            __half* __restrict__ out,
                                                            int R, int C) {
    __shared__ float tile[32][33];
    int c0 = blockIdx.x * 32, r0 = blockIdx.y * 32;
    int x = threadIdx.x, y = threadIdx.y;  // block (32, 8)
    #pragma unroll
    for (int j = 0; j < 32; j += 8)
        tile[y + j][x] = in[(size_t)(r0 + y + j) * C + (c0 + x)];
    __syncthreads();
    #pragma unroll
    for (int j = 0; j < 32; j += 8)
        out[(size_t)(c0 + y + j) * R + (r0 + x)] = __float2half_rn(tile[x][y + j]);
}

// ---------------- mma.sync GEMM: 128 threads / 4 warps, warp tile 64x64, 2 CTAs/SM ----------------
template<int MODE>
__global__ void __launch_bounds__(128, 2)
gemm_f16_kernel(const __half* __restrict__ A, const __half* __restrict__ B,
                const float* __restrict__ bias, void* __restrict__ Cout,
                int K, int nk) {
    extern __shared__ char smem[];
    const uint32_t sb = smem_u32(smem);
    const int tid  = threadIdx.x;
    const int wid  = tid >> 5, lane = tid & 31;
    const int wm   = wid & 1;            // 0..1 -> M offset (x64)
    const int wn   = wid >> 1;           // 0..1 -> N offset (x64)
    const int m0   = blockIdx.y * BM;
    const int n0   = blockIdx.x * BN;

    const int cr = tid >> 3;             // 0..15
    const int cc = (tid & 7) * 16;       // byte offset within 128B K-slice

    const char* gA = reinterpret_cast<const char*>(A) + ((size_t)(m0 + cr) * K) * 2 + cc;
    const char* gB = reinterpret_cast<const char*>(B) + ((size_t)(n0 + cr) * K) * 2 + cc;
    const size_t rstride = (size_t)16 * K * 2;   // +16 rows

    auto issue_stage = [&](int kc, int s) {
        const uint32_t abase = sb + s * STAGE_BYTES;
        const uint32_t bbase = abase + BM * ROWB;
        const size_t koff = (size_t)kc * (BK * 2);
        #pragma unroll
        for (int h = 0; h < 8; h++)  // A: 128 rows
            CP_ASYNC16(abase + (cr + h * 16) * ROWB + cc, gA + koff + h * rstride);
        #pragma unroll
        for (int h = 0; h < 8; h++)  // B: 128 rows
            CP_ASYNC16(bbase + (cr + h * 16) * ROWB + cc, gB + koff + h * rstride);
    };

    const int a_row = lane & 15, a_k8 = lane >> 4;                             // A m16k16 .x4
    const int b_row = (lane & 7) + ((lane >> 4) << 3), b_k8 = (lane >> 3) & 1; // B 2x n8k16 .x4

    float acc[4][8][4];
    #pragma unroll
    for (int i = 0; i < 4; i++)
        #pragma unroll
        for (int j = 0; j < 8; j++)
            #pragma unroll
            for (int r = 0; r < 4; r++) acc[i][j][r] = 0.f;

    issue_stage(0, 0); CP_ASYNC_COMMIT();
    if (nk > 1) issue_stage(1, 1); CP_ASYNC_COMMIT();

    int s = 0, s2 = 2;
    for (int kc = 0; kc < nk; kc++) {
        CP_ASYNC_WAIT1();
        __syncthreads();

        if (kc + 2 < nk) issue_stage(kc + 2, s2);
        CP_ASYNC_COMMIT();

        const uint32_t abase = sb + s * STAGE_BYTES;
        const uint32_t bbase = abase + BM * ROWB;

        #pragma unroll
        for (int kk = 0; kk < 4; kk++) {
            uint32_t af[4][4], bf[8][2];
            #pragma unroll
            for (int mi = 0; mi < 4; mi++) {
                uint32_t addr = abase + (wm * 64 + mi * 16 + a_row) * ROWB + (kk * 2 + a_k8) * 16;
                ldm_x4(af[mi][0], af[mi][1], af[mi][2], af[mi][3], addr);
            }
            #pragma unroll
            for (int nb = 0; nb < 4; nb++) {
                uint32_t addr = bbase + (wn * 64 + nb * 16 + b_row) * ROWB + (kk * 2 + b_k8) * 16;
                uint32_t r0, r1, r2, r3;
                ldm_x4(r0, r1, r2, r3, addr);
                bf[nb * 2][0] = r0;     bf[nb * 2][1] = r1;
                bf[nb * 2 + 1][0] = r2; bf[nb * 2 + 1][1] = r3;
            }
            #pragma unroll
            for (int mi = 0; mi < 4; mi++)
                #pragma unroll
                for (int nj = 0; nj < 8; nj++)
                    mma16816(acc[mi][nj], af[mi], bf[nj]);
        }
        s = (s == 2) ? 0 : s + 1;
        s2 = (s2 == 2) ? 0 : s2 + 1;
    }

    const int tq = lane >> 2, tr = lane & 3;
    #pragma unroll
    for (int nj = 0; nj < 8; nj++) {
        const int col = n0 + wn * 64 + nj * 8 + tr * 2;
        const float bx = bias[col], by = bias[col + 1];
        #pragma unroll
        for (int mi = 0; mi < 4; mi++) {
            const int row = m0 + wm * 64 + mi * 16 + tq;
            if (MODE == 0) {
                __half* C = reinterpret_cast<__half*>(Cout);
                __half2 h0 = __floats2half2_rn(acc[mi][nj][0] + bx, acc[mi][nj][1] + by);
                __half2 h1 = __floats2half2_rn(acc[mi][nj][2] + bx, acc[mi][nj][3] + by);
                *reinterpret_cast<__half2*>(C + (size_t)row * HID + col) = h0;
                *reinterpret_cast<__half2*>(C + (size_t)(row + 8) * HID + col) = h1;
            } else {
                float* C = reinterpret_cast<float*>(Cout);
                float2 f0 = make_float2(fmaxf(acc[mi][nj][0] + bx, 0.f), fmaxf(acc[mi][nj][1] + by, 0.f));
                float2 f1 = make_float2(fmaxf(acc[mi][nj][2] + bx, 0.f), fmaxf(acc[mi][nj][3] + by, 0.f));
                *reinterpret_cast<float2*>(C + (size_t)row * HID + col) = f0;
                *reinterpret_cast<float2*>(C + (size_t)(row + 8) * HID + col) = f1;
            }
        }
    }
}

// ---------------- heads: logits softmax + box regression ----------------
__global__ void __launch_bounds__(128) heads_kernel(const float* __restrict__ H,
                                                    const float* __restrict__ Wc, const float* __restrict__ bc,
                                                    const float* __restrict__ Wr, const float* __restrict__ br,
                                                    float* __restrict__ out) {
    const int row = blockIdx.x;
    const int tid = threadIdx.x, lane = tid & 31, w = tid >> 5;
    __shared__ float part[4 * 16];
    __shared__ float res[16];

    float acc[16];
    #pragma unroll
    for (int o = 0; o < 16; o++) acc[o] = 0.f;

    const float* h = H + (size_t)row * HID;
    const float4* Wc4 = reinterpret_cast<const float4*>(Wc);
    const float4* Wr4 = reinterpret_cast<const float4*>(Wr);
    for (int k = tid; k < HID; k += 128) {
        float hv = h[k];
        float4 c = Wc4[k];
        acc[0] += hv * c.x; acc[1] += hv * c.y; acc[2] += hv * c.z; acc[3] += hv * c.w;
        float4 r0 = Wr4[k * 3], r1 = Wr4[k * 3 + 1], r2 = Wr4[k * 3 + 2];
        acc[4]  += hv * r0.x; acc[5]  += hv * r0.y; acc[6]  += hv * r0.z; acc[7]  += hv * r0.w;
        acc[8]  += hv * r1.x; acc[9]  += hv * r1.y; acc[10] += hv * r1.z; acc[11] += hv * r1.w;
        acc[12] += hv * r2.x; acc[13] += hv * r2.y; acc[14] += hv * r2.z; acc[15] += hv * r2.w;
    }
    #pragma unroll
    for (int o = 0; o < 16; o++) {
        float v = acc[o];
        v += __shfl_xor_sync(0xffffffffu, v, 16);
        v += __shfl_xor_sync(0xffffffffu, v, 8);
        v += __shfl_xor_sync(0xffffffffu, v, 4);
        v += __shfl_xor_sync(0xffffffffu, v, 2);
        v += __shfl_xor_sync(0xffffffffu, v, 1);
        if (lane == 0) part[w * 16 + o] = v;
    }
    __syncthreads();
    if (tid < 16) {
        float v = part[tid] + part[16 + tid] + part[32 + tid] + part[48 + tid];
        v += (tid < 4) ? bc[tid] : br[tid - 4];
        res[tid] = v;
    }
    __syncthreads();
    if (tid == 0) {
        float m = fmaxf(fmaxf(res[0], res[1]), fmaxf(res[2], res[3]));
        float e0 = expf(res[0] - m), e1 = expf(res[1] - m), e2 = expf(res[2] - m), e3 = expf(res[3] - m);
        float inv = 1.f / (e0 + e1 + e2 + e3);
        out[(size_t)row * 4 + 0] = e0 * inv;
        out[(size_t)row * 4 + 1] = e1 * inv;
        out[(size_t)row * 4 + 2] = e2 * inv;
        out[(size_t)row * 4 + 3] = e3 * inv;
    }
    if (tid >= 4 && tid < 16)
        out[(size_t)NROWS * 4 + (size_t)row * 12 + (tid - 4)] = res[tid];
}

// ---------------- launch (fork-join multi-stream graph) ----------------
extern "C" void kernel_launch(void* const* d_in, const int* in_sizes, int n_in,
                              void* d_out, int out_size) {
    (void)in_sizes; (void)n_in; (void)out_size;
    const float* X  = (const float*)d_in[0];
    const float* W1 = (const float*)d_in[1];
    const float* b1 = (const float*)d_in[2];
    const float* W2 = (const float*)d_in[3];
    const float* b2 = (const float*)d_in[4];
    const float* Wc = (const float*)d_in[5];
    const float* bc = (const float*)d_in[6];
    const float* Wr = (const float*)d_in[7];
    const float* br = (const float*)d_in[8];
    float* out = (float*)d_out;

    void *pXh, *pW1T, *pW2T, *pH1, *pH2;
    cudaGetSymbolAddress(&pXh,  g_Xh);
    cudaGetSymbolAddress(&pW1T, g_W1T);
    cudaGetSymbolAddress(&pW2T, g_W2T);
    cudaGetSymbolAddress(&pH1,  g_H1);
    cudaGetSymbolAddress(&pH2,  g_H2);
    __half* Xh  = (__half*)pXh;
    __half* W1T = (__half*)pW1T;
    __half* W2T = (__half*)pW2T;
    __half* H1  = (__half*)pH1;
    float*  H2  = (float*)pH2;

    cudaFuncSetAttribute(gemm_f16_kernel<0>, cudaFuncAttributeMaxDynamicSharedMemorySize, SMEM_BYTES);
    cudaFuncSetAttribute(gemm_f16_kernel<1>, cudaFuncAttributeMaxDynamicSharedMemorySize, SMEM_BYTES);

    // persistent side streams/events (host objects only; created on first,
    // uncaptured, correctness call — no device memory involved)
    static cudaStream_t sT = [] { cudaStream_t s; cudaStreamCreateWithFlags(&s, cudaStreamNonBlocking); return s; }();
    static cudaStream_t sC = [] { cudaStream_t s; cudaStreamCreateWithFlags(&s, cudaStreamNonBlocking); return s; }();
    static cudaEvent_t  eFork  = [] { cudaEvent_t e; cudaEventCreateWithFlags(&e, cudaEventDisableTiming); return e; }();
    static cudaEvent_t  eConv0 = [] { cudaEvent_t e; cudaEventCreateWithFlags(&e, cudaEventDisableTiming); return e; }();
    static cudaEvent_t  eT     = [] { cudaEvent_t e; cudaEventCreateWithFlags(&e, cudaEventDisableTiming); return e; }();
    static cudaEvent_t  eConv1 = [] { cudaEvent_t e; cudaEventCreateWithFlags(&e, cudaEventDisableTiming); return e; }();

    const size_t halfElems = (size_t)(NROWS / 2) * DIN;   // X half, in floats
    const size_t n8h = halfElems / 8;

    // fork transposes onto sT (concurrent with conv0 on main stream)
    cudaEventRecord(eFork, 0);
    cudaStreamWaitEvent(sT, eFork, 0);
    transpose_f32_to_f16<<<dim3(HID / 32, DIN / 32), dim3(32, 8), 0, sT>>>(W1, W1T, DIN, HID);
    transpose_f32_to_f16<<<dim3(HID / 32, HID / 32), dim3(32, 8), 0, sT>>>(W2, W2T, HID, HID);
    cudaEventRecord(eT, sT);

    // main: convert first half of X
    f32_to_f16_kernel<<<(unsigned)((n8h + 255) / 256), 256>>>(X, Xh, n8h);
    cudaEventRecord(eConv0, 0);

    // sC: convert second half of X, concurrent with gemm1a
    cudaStreamWaitEvent(sC, eConv0, 0);
    f32_to_f16_kernel<<<(unsigned)((n8h + 255) / 256), 256, 0, sC>>>(X + halfElems, Xh + halfElems, n8h);
    cudaEventRecord(eConv1, sC);

    // main: gemm1a on rows [0, 4096)  (needs W1T + conv0)
    cudaStreamWaitEvent(0, eT, 0);
    gemm_f16_kernel<0><<<dim3(HID / BN, (NROWS / 2) / BM), 128, SMEM_BYTES>>>(
        Xh, W1T, b1, H1, DIN, DIN / BK);

    // main: gemm1b on rows [4096, 8192)  (needs conv1)
    cudaStreamWaitEvent(0, eConv1, 0);
    gemm_f16_kernel<0><<<dim3(HID / BN, (NROWS / 2) / BM), 128, SMEM_BYTES>>>(
        Xh + halfElems, W1T, b1, H1 + (size_t)(NROWS / 2) * HID, DIN, DIN / BK);

    // H2 = relu(H1 @ W2 + b2)
    gemm_f16_kernel<1><<<dim3(HID / BN, NROWS / BM), 128, SMEM_BYTES>>>(
        H1, W2T, b2, H2, HID, HID / BK);

    // heads
    heads_kernel<<<NROWS, 128>>>(H2, Wc, bc, Wr, br, out);
}

// round 10
// speedup vs baseline: 1.0235x; 1.0235x over previous
#include <cuda_runtime.h>
#include <cuda_fp16.h>
#include <cstdint>

// ---------------- problem constants ----------------
#define NROWS 8192
#define DIN   12544
#define HID   1024

// ---------------- GEMM tile config: 128x128 tile, 4 warps (64x64 warp tile) ----------------
#define BM 128
#define BN 128
#define BK 64
#define ROWB 144                           // 128B data + 16B pad (conflict-free ldmatrix)
#define STAGE_BYTES ((BM + BN) * ROWB)     // 36864
#define SMEM_BYTES (3 * STAGE_BYTES)       // 110592 -> 2 CTAs/SM

// prep kernel sections
#define CONV_BLOCKS 50176                  // 8192*12544/8/256
#define W1T_BX 32
#define W1T_BLOCKS (W1T_BX * (DIN / 32))   // 12544
#define W2T_BX 32
#define W2T_BLOCKS (W2T_BX * (HID / 32))   // 1024
#define PREP_BLOCKS (CONV_BLOCKS + W1T_BLOCKS + W2T_BLOCKS)

// ---------------- device scratch ----------------
__device__ __align__(256) __half g_Xh [(size_t)NROWS * DIN];
__device__ __align__(256) __half g_W1T[(size_t)HID * DIN];
__device__ __align__(256) __half g_W2T[(size_t)HID * HID];
__device__ __align__(256) __half g_H1 [(size_t)NROWS * HID];
__device__ __align__(256) __half g_H2 [(size_t)NROWS * HID];

// ---------------- PTX helpers ----------------
__device__ __forceinline__ uint32_t smem_u32(const void* p) {
    uint32_t a;
    asm("{ .reg .u64 t; cvta.to.shared.u64 t, %1; cvt.u32.u64 %0, t; }" : "=r"(a) : "l"(p));
    return a;
}

#define CP_ASYNC16(dst, src) \
    asm volatile("cp.async.cg.shared.global [%0], [%1], 16;" :: "r"(dst), "l"(src) : "memory")
#define CP_ASYNC_COMMIT() asm volatile("cp.async.commit_group;" ::: "memory")
#define CP_ASYNC_WAIT1()  asm volatile("cp.async.wait_group 1;" ::: "memory")

__device__ __forceinline__ void ldm_x4(uint32_t& r0, uint32_t& r1, uint32_t& r2, uint32_t& r3,
                                       uint32_t addr) {
    asm volatile("ldmatrix.sync.aligned.m8n8.x4.shared.b16 {%0,%1,%2,%3}, [%4];"
                 : "=r"(r0), "=r"(r1), "=r"(r2), "=r"(r3) : "r"(addr));
}

__device__ __forceinline__ void mma16816(float* d, const uint32_t* a, const uint32_t* b) {
    asm volatile(
        "mma.sync.aligned.m16n8k16.row.col.f32.f16.f16.f32 "
        "{%0,%1,%2,%3}, {%4,%5,%6,%7}, {%8,%9}, {%0,%1,%2,%3};"
        : "+f"(d[0]), "+f"(d[1]), "+f"(d[2]), "+f"(d[3])
        : "r"(a[0]), "r"(a[1]), "r"(a[2]), "r"(a[3]), "r"(b[0]), "r"(b[1]));
}

// ---------------- prep: X convert + W1 transpose + W2 transpose, one launch ----------------
__global__ void __launch_bounds__(256) prep_kernel(const float* __restrict__ X, __half* __restrict__ Xh,
                                                   const float* __restrict__ W1, __half* __restrict__ W1T,
                                                   const float* __restrict__ W2, __half* __restrict__ W2T) {
    __shared__ float tile[32][33];
    const int b   = blockIdx.x;
    const int tid = threadIdx.x;

    if (b < CONV_BLOCKS) {
        // ---- X f32 -> f16, 8 elems/thread ----
        size_t i = (size_t)b * 256 + tid;
        const float4* p = reinterpret_cast<const float4*>(X) + i * 2;
        float4 a = p[0], c = p[1];
        __half2 h0 = __floats2half2_rn(a.x, a.y), h1 = __floats2half2_rn(a.z, a.w);
        __half2 h2 = __floats2half2_rn(c.x, c.y), h3 = __floats2half2_rn(c.z, c.w);
        uint4 v;
        v.x = *reinterpret_cast<uint32_t*>(&h0);
        v.y = *reinterpret_cast<uint32_t*>(&h1);
        v.z = *reinterpret_cast<uint32_t*>(&h2);
        v.w = *reinterpret_cast<uint32_t*>(&h3);
        reinterpret_cast<uint4*>(Xh)[i] = v;
        return;
    }

    // ---- transpose sections: in [R,C] f32 -> out [C,R] f16 ----
    const float* in; __half* out; int R, C, idx, bx;
    if (b < CONV_BLOCKS + W1T_BLOCKS) {
        idx = b - CONV_BLOCKS; in = W1; out = W1T; R = DIN; C = HID; bx = W1T_BX;
    } else {
        idx = b - CONV_BLOCKS - W1T_BLOCKS; in = W2; out = W2T; R = HID; C = HID; bx = W2T_BX;
    }
    const int c0 = (idx % bx) * 32, r0 = (idx / bx) * 32;
    const int x = tid & 31, y = tid >> 5;  // (32, 8)
    #pragma unroll
    for (int j = 0; j < 32; j += 8)
        tile[y + j][x] = in[(size_t)(r0 + y + j) * C + (c0 + x)];
    __syncthreads();
    #pragma unroll
    for (int j = 0; j < 32; j += 8)
        out[(size_t)(c0 + y + j) * R + (r0 + x)] = __float2half_rn(tile[x][y + j]);
}

// ---------------- mma.sync GEMM: 128 threads / 4 warps, warp tile 64x64, 2 CTAs/SM ----------------
// MODE 0: out = half, +bias           (GEMM1 -> H1)
// MODE 1: out = half, relu(+bias)     (GEMM2 -> H2, fp32 math then f16 store)
template<int MODE>
__global__ void __launch_bounds__(128, 2)
gemm_f16_kernel(const __half* __restrict__ A, const __half* __restrict__ B,
                const float* __restrict__ bias, void* __restrict__ Cout,
                int K, int nk) {
    extern __shared__ char smem[];
    const uint32_t sb = smem_u32(smem);
    const int tid  = threadIdx.x;
    const int wid  = tid >> 5, lane = tid & 31;
    const int wm   = wid & 1;            // 0..1 -> M offset (x64)
    const int wn   = wid >> 1;           // 0..1 -> N offset (x64)
    const int m0   = blockIdx.y * BM;
    const int n0   = blockIdx.x * BN;

    const int cr = tid >> 3;             // 0..15
    const int cc = (tid & 7) * 16;       // byte offset within 128B K-slice

    const char* gA = reinterpret_cast<const char*>(A) + ((size_t)(m0 + cr) * K) * 2 + cc;
    const char* gB = reinterpret_cast<const char*>(B) + ((size_t)(n0 + cr) * K) * 2 + cc;
    const size_t rstride = (size_t)16 * K * 2;   // +16 rows

    auto issue_stage = [&](int kc, int s) {
        const uint32_t abase = sb + s * STAGE_BYTES;
        const uint32_t bbase = abase + BM * ROWB;
        const size_t koff = (size_t)kc * (BK * 2);
        #pragma unroll
        for (int h = 0; h < 8; h++)  // A: 128 rows
            CP_ASYNC16(abase + (cr + h * 16) * ROWB + cc, gA + koff + h * rstride);
        #pragma unroll
        for (int h = 0; h < 8; h++)  // B: 128 rows
            CP_ASYNC16(bbase + (cr + h * 16) * ROWB + cc, gB + koff + h * rstride);
    };

    const int a_row = lane & 15, a_k8 = lane >> 4;                             // A m16k16 .x4
    const int b_row = (lane & 7) + ((lane >> 4) << 3), b_k8 = (lane >> 3) & 1; // B 2x n8k16 .x4

    float acc[4][8][4];
    #pragma unroll
    for (int i = 0; i < 4; i++)
        #pragma unroll
        for (int j = 0; j < 8; j++)
            #pragma unroll
            for (int r = 0; r < 4; r++) acc[i][j][r] = 0.f;

    issue_stage(0, 0); CP_ASYNC_COMMIT();
    if (nk > 1) issue_stage(1, 1); CP_ASYNC_COMMIT();

    int s = 0, s2 = 2;
    for (int kc = 0; kc < nk; kc++) {
        CP_ASYNC_WAIT1();
        __syncthreads();

        if (kc + 2 < nk) issue_stage(kc + 2, s2);
        CP_ASYNC_COMMIT();

        const uint32_t abase = sb + s * STAGE_BYTES;
        const uint32_t bbase = abase + BM * ROWB;

        #pragma unroll
        for (int kk = 0; kk < 4; kk++) {
            uint32_t af[4][4], bf[8][2];
            #pragma unroll
            for (int mi = 0; mi < 4; mi++) {
                uint32_t addr = abase + (wm * 64 + mi * 16 + a_row) * ROWB + (kk * 2 + a_k8) * 16;
                ldm_x4(af[mi][0], af[mi][1], af[mi][2], af[mi][3], addr);
            }
            #pragma unroll
            for (int nb = 0; nb < 4; nb++) {
                uint32_t addr = bbase + (wn * 64 + nb * 16 + b_row) * ROWB + (kk * 2 + b_k8) * 16;
                uint32_t r0, r1, r2, r3;
                ldm_x4(r0, r1, r2, r3, addr);
                bf[nb * 2][0] = r0;     bf[nb * 2][1] = r1;
                bf[nb * 2 + 1][0] = r2; bf[nb * 2 + 1][1] = r3;
            }
            #pragma unroll
            for (int mi = 0; mi < 4; mi++)
                #pragma unroll
                for (int nj = 0; nj < 8; nj++)
                    mma16816(acc[mi][nj], af[mi], bf[nj]);
        }
        s = (s == 2) ? 0 : s + 1;
        s2 = (s2 == 2) ? 0 : s2 + 1;
    }

    const int tq = lane >> 2, tr = lane & 3;
    #pragma unroll
    for (int nj = 0; nj < 8; nj++) {
        const int col = n0 + wn * 64 + nj * 8 + tr * 2;
        const float bx = bias[col], by = bias[col + 1];
        #pragma unroll
        for (int mi = 0; mi < 4; mi++) {
            const int row = m0 + wm * 64 + mi * 16 + tq;
            __half* C = reinterpret_cast<__half*>(Cout);
            if (MODE == 0) {
                __half2 h0 = __floats2half2_rn(acc[mi][nj][0] + bx, acc[mi][nj][1] + by);
                __half2 h1 = __floats2half2_rn(acc[mi][nj][2] + bx, acc[mi][nj][3] + by);
                *reinterpret_cast<__half2*>(C + (size_t)row * HID + col) = h0;
                *reinterpret_cast<__half2*>(C + (size_t)(row + 8) * HID + col) = h1;
            } else {
                __half2 h0 = __floats2half2_rn(fmaxf(acc[mi][nj][0] + bx, 0.f),
                                               fmaxf(acc[mi][nj][1] + by, 0.f));
                __half2 h1 = __floats2half2_rn(fmaxf(acc[mi][nj][2] + bx, 0.f),
                                               fmaxf(acc[mi][nj][3] + by, 0.f));
                *reinterpret_cast<__half2*>(C + (size_t)row * HID + col) = h0;
                *reinterpret_cast<__half2*>(C + (size_t)(row + 8) * HID + col) = h1;
            }
        }
    }
}

// ---------------- heads: logits softmax + box regression (reads f16 H2) ----------------
__global__ void __launch_bounds__(128) heads_kernel(const __half* __restrict__ H,
                                                    const float* __restrict__ Wc, const float* __restrict__ bc,
                                                    const float* __restrict__ Wr, const float* __restrict__ br,
                                                    float* __restrict__ out) {
    const int row = blockIdx.x;
    const int tid = threadIdx.x, lane = tid & 31, w = tid >> 5;
    __shared__ float part[4 * 16];
    __shared__ float res[16];

    float acc[16];
    #pragma unroll
    for (int o = 0; o < 16; o++) acc[o] = 0.f;

    const __half* h = H + (size_t)row * HID;
    const float4* Wc4 = reinterpret_cast<const float4*>(Wc);
    const float4* Wr4 = reinterpret_cast<const float4*>(Wr);
    for (int k = tid; k < HID; k += 128) {
        float hv = __half2float(h[k]);
        float4 c = Wc4[k];
        acc[0] += hv * c.x; acc[1] += hv * c.y; acc[2] += hv * c.z; acc[3] += hv * c.w;
        float4 r0 = Wr4[k * 3], r1 = Wr4[k * 3 + 1], r2 = Wr4[k * 3 + 2];
        acc[4]  += hv * r0.x; acc[5]  += hv * r0.y; acc[6]  += hv * r0.z; acc[7]  += hv * r0.w;
        acc[8]  += hv * r1.x; acc[9]  += hv * r1.y; acc[10] += hv * r1.z; acc[11] += hv * r1.w;
        acc[12] += hv * r2.x; acc[13] += hv * r2.y; acc[14] += hv * r2.z; acc[15] += hv * r2.w;
    }
    #pragma unroll
    for (int o = 0; o < 16; o++) {
        float v = acc[o];
        v += __shfl_xor_sync(0xffffffffu, v, 16);
        v += __shfl_xor_sync(0xffffffffu, v, 8);
        v += __shfl_xor_sync(0xffffffffu, v, 4);
        v += __shfl_xor_sync(0xffffffffu, v, 2);
        v += __shfl_xor_sync(0xffffffffu, v, 1);
        if (lane == 0) part[w * 16 + o] = v;
    }
    __syncthreads();
    if (tid < 16) {
        float v = part[tid] + part[16 + tid] + part[32 + tid] + part[48 + tid];
        v += (tid < 4) ? bc[tid] : br[tid - 4];
        res[tid] = v;
    }
    __syncthreads();
    if (tid == 0) {
        float m = fmaxf(fmaxf(res[0], res[1]), fmaxf(res[2], res[3]));
        float e0 = expf(res[0] - m), e1 = expf(res[1] - m), e2 = expf(res[2] - m), e3 = expf(res[3] - m);
        float inv = 1.f / (e0 + e1 + e2 + e3);
        out[(size_t)row * 4 + 0] = e0 * inv;
        out[(size_t)row * 4 + 1] = e1 * inv;
        out[(size_t)row * 4 + 2] = e2 * inv;
        out[(size_t)row * 4 + 3] = e3 * inv;
    }
    if (tid >= 4 && tid < 16)
        out[(size_t)NROWS * 4 + (size_t)row * 12 + (tid - 4)] = res[tid];
}

// ---------------- launch (single stream, serial) ----------------
extern "C" void kernel_launch(void* const* d_in, const int* in_sizes, int n_in,
                              void* d_out, int out_size) {
    (void)in_sizes; (void)n_in; (void)out_size;
    const float* X  = (const float*)d_in[0];
    const float* W1 = (const float*)d_in[1];
    const float* b1 = (const float*)d_in[2];
    const float* W2 = (const float*)d_in[3];
    const float* b2 = (const float*)d_in[4];
    const float* Wc = (const float*)d_in[5];
    const float* bc = (const float*)d_in[6];
    const float* Wr = (const float*)d_in[7];
    const float* br = (const float*)d_in[8];
    float* out = (float*)d_out;

    void *pXh, *pW1T, *pW2T, *pH1, *pH2;
    cudaGetSymbolAddress(&pXh,  g_Xh);
    cudaGetSymbolAddress(&pW1T, g_W1T);
    cudaGetSymbolAddress(&pW2T, g_W2T);
    cudaGetSymbolAddress(&pH1,  g_H1);
    cudaGetSymbolAddress(&pH2,  g_H2);

    cudaFuncSetAttribute(gemm_f16_kernel<0>, cudaFuncAttributeMaxDynamicSharedMemorySize, SMEM_BYTES);
    cudaFuncSetAttribute(gemm_f16_kernel<1>, cudaFuncAttributeMaxDynamicSharedMemorySize, SMEM_BYTES);

    // 1) prep: X -> fp16, W1 -> W1T (f16), W2 -> W2T (f16), one launch
    prep_kernel<<<PREP_BLOCKS, 256>>>(X, (__half*)pXh, W1, (__half*)pW1T, W2, (__half*)pW2T);
    // 2) H1 = X @ W1 + b1          (f16 out)
    gemm_f16_kernel<0><<<dim3(HID / BN, NROWS / BM), 128, SMEM_BYTES>>>(
        (const __half*)pXh, (const __half*)pW1T, b1, pH1, DIN, DIN / BK);
    // 3) H2 = relu(H1 @ W2 + b2)   (f16 out)
    gemm_f16_kernel<1><<<dim3(HID / BN, NROWS / BM), 128, SMEM_BYTES>>>(
        (const __half*)pH1, (const __half*)pW2T, b2, pH2, HID, HID / BK);
    // 4) heads
    heads_kernel<<<NROWS, 128>>>((const __half*)pH2, Wc, bc, Wr, br, out);
}